// round 7
// baseline (speedup 1.0000x reference)
#include <cuda_runtime.h>

// Leapfrog integrator, softened central potential:
//   accel(q) = -q / (r*(r+1)^2 + 1e-12)
//
// R5: 2 particle-pairs per thread. Each pair = (lead, trail) of one particle
// packed in f32x2 registers (shared dt); the two pairs are independent
// dependency chains -> ILP covers the RSQ/RCP latency at low occupancy.
// Half-kick fusion: consecutive half-kicks with the same cached accel are
// merged into one full dt-kick; h*a0 pre-kick, -h*a_last post-correction.
//
// Inputs: d_in[0]=ts f32[N], d_in[1]=w0_lead f32[N,6], d_in[2]=w0_trail f32[N,6],
//         d_in[3]=n_steps i32[1]
// Output: f32[2N,6], row 2i = trail_i, row 2i+1 = lead_i.

typedef unsigned long long u64;

__device__ __forceinline__ u64 pk(float lo, float hi) {
    u64 r; asm("mov.b64 %0, {%1,%2};" : "=l"(r) : "f"(lo), "f"(hi)); return r;
}
__device__ __forceinline__ void upk(u64 v, float& lo, float& hi) {
    asm("mov.b64 {%0,%1}, %2;" : "=f"(lo), "=f"(hi) : "l"(v));
}
__device__ __forceinline__ u64 fma2(u64 a, u64 b, u64 c) {
    u64 d; asm("fma.rn.f32x2 %0, %1, %2, %3;" : "=l"(d) : "l"(a), "l"(b), "l"(c)); return d;
}
__device__ __forceinline__ u64 mul2(u64 a, u64 b) {
    u64 d; asm("mul.rn.f32x2 %0, %1, %2;" : "=l"(d) : "l"(a), "l"(b)); return d;
}
__device__ __forceinline__ u64 add2(u64 a, u64 b) {
    u64 d; asm("add.rn.f32x2 %0, %1, %2;" : "=l"(d) : "l"(a), "l"(b)); return d;
}
__device__ __forceinline__ float frsqrt_fast(float x) {
    float r; asm("rsqrt.approx.f32 %0, %1;" : "=f"(r) : "f"(x)); return r;
}
__device__ __forceinline__ float frcp_fast(float x) {
    float r; asm("rcp.approx.f32 %0, %1;" : "=f"(r) : "f"(x)); return r;
}

// Packed accel direction A = c*q with c = 1/(r(r+1)^2+eps) > 0.
// Kicks multiply by a negative packed step constant.
#define ACCEL(X, Y, Z, AX, AY, AZ)                         \
    do {                                                   \
        u64 S_ = mul2(X, X);                               \
        S_ = fma2(Y, Y, S_);                               \
        S_ = fma2(Z, Z, S_);                               \
        float s0_, s1_; upk(S_, s0_, s1_);                 \
        u64 RI_ = pk(frsqrt_fast(s0_), frsqrt_fast(s1_));  \
        u64 R_  = mul2(S_, RI_);                           \
        u64 T_  = add2(R_, ONE2);                          \
        u64 U_  = mul2(R_, T_);                            \
        u64 D_  = fma2(U_, T_, EPS2);                      \
        float d0_, d1_; upk(D_, d0_, d1_);                 \
        u64 C_  = pk(frcp_fast(d0_), frcp_fast(d1_));      \
        AX = mul2(C_, X);                                  \
        AY = mul2(C_, Y);                                  \
        AZ = mul2(C_, Z);                                  \
    } while (0)

// drift + accel + full kick (fused half-kicks), one pair
#define STEP(X, Y, Z, PX, PY, PZ, AX, AY, AZ, DT2, DTN2)   \
    do {                                                   \
        X = fma2(DT2, PX, X);                              \
        Y = fma2(DT2, PY, Y);                              \
        Z = fma2(DT2, PZ, Z);                              \
        ACCEL(X, Y, Z, AX, AY, AZ);                        \
        PX = fma2(DTN2, AX, PX);                           \
        PY = fma2(DTN2, AY, PY);                           \
        PZ = fma2(DTN2, AZ, PZ);                           \
    } while (0)

__global__ void __launch_bounds__(32)
leapfrog4_kernel(const float* __restrict__ ts,
                 const float* __restrict__ w_lead,
                 const float* __restrict__ w_trail,
                 const int* __restrict__ n_steps_p,
                 float* __restrict__ out,
                 int n) {
    int idx  = blockIdx.x * 32 + threadIdx.x;
    int half = (n + 1) >> 1;
    if (idx >= half) return;

    const int iA = idx;
    const int iB = idx + half;
    const bool hasB = (iB < n);

    const int nst = *n_steps_p;
    const float t_f = ts[n - 1] + 0.001f;
    const float inv_nst = frcp_fast((float)nst) * 0.0f + 1.0f / (float)nst; // exact path below
    (void)inv_nst;

    const u64 ONE2 = pk(1.0f, 1.0f);
    const u64 EPS2 = pk(1e-12f, 1e-12f);

    // ---- pair A ----
    float dtA = (t_f - ts[iA]) / (float)nst;
    float hA  = 0.5f * dtA;
    const float2* lpA = reinterpret_cast<const float2*>(w_lead  + 6 * (size_t)iA);
    const float2* tpA = reinterpret_cast<const float2*>(w_trail + 6 * (size_t)iA);
    float2 a0 = lpA[0], a1 = lpA[1], a2 = lpA[2];
    float2 b0 = tpA[0], b1 = tpA[1], b2 = tpA[2];
    u64 XA  = pk(a0.x, b0.x), YA  = pk(a0.y, b0.y), ZA  = pk(a1.x, b1.x);
    u64 PXA = pk(a1.y, b1.y), PYA = pk(a2.x, b2.x), PZA = pk(a2.y, b2.y);
    const u64 DT2A  = pk(dtA, dtA);
    const u64 DTN2A = pk(-dtA, -dtA);
    const u64 HN2A  = pk(-hA, -hA);
    const u64 HP2A  = pk(hA, hA);

    // ---- pair B ----
    int iBc = hasB ? iB : iA;  // clamp to keep loads legal; result discarded
    float dtB = (t_f - ts[iBc]) / (float)nst;
    float hB  = 0.5f * dtB;
    const float2* lpB = reinterpret_cast<const float2*>(w_lead  + 6 * (size_t)iBc);
    const float2* tpB = reinterpret_cast<const float2*>(w_trail + 6 * (size_t)iBc);
    float2 c0 = lpB[0], c1 = lpB[1], c2 = lpB[2];
    float2 d0 = tpB[0], d1 = tpB[1], d2 = tpB[2];
    u64 XB  = pk(c0.x, d0.x), YB  = pk(c0.y, d0.y), ZB  = pk(c1.x, d1.x);
    u64 PXB = pk(c1.y, d1.y), PYB = pk(c2.x, d2.x), PZB = pk(c2.y, d2.y);
    const u64 DT2B  = pk(dtB, dtB);
    const u64 DTN2B = pk(-dtB, -dtB);
    const u64 HN2B  = pk(-hB, -hB);
    const u64 HP2B  = pk(hB, hB);

    u64 AXA, AYA, AZA, AXB, AYB, AZB;

    // pre-kick: p += h * a(q0)
    ACCEL(XA, YA, ZA, AXA, AYA, AZA);
    ACCEL(XB, YB, ZB, AXB, AYB, AZB);
    PXA = fma2(HN2A, AXA, PXA); PYA = fma2(HN2A, AYA, PYA); PZA = fma2(HN2A, AZA, PZA);
    PXB = fma2(HN2B, AXB, PXB); PYB = fma2(HN2B, AYB, PYB); PZB = fma2(HN2B, AZB, PZB);

    if (nst == 64) {
#pragma unroll 8
        for (int s = 0; s < 64; s++) {
            STEP(XA, YA, ZA, PXA, PYA, PZA, AXA, AYA, AZA, DT2A, DTN2A);
            STEP(XB, YB, ZB, PXB, PYB, PZB, AXB, AYB, AZB, DT2B, DTN2B);
        }
    } else {
#pragma unroll 2
        for (int s = 0; s < nst; s++) {
            STEP(XA, YA, ZA, PXA, PYA, PZA, AXA, AYA, AZA, DT2A, DTN2A);
            STEP(XB, YB, ZB, PXB, PYB, PZB, AXB, AYB, AZB, DT2B, DTN2B);
        }
    }

    // post-correction: loop over-kicked by h*a_last -> p += h*a_last (undo)
    PXA = fma2(HP2A, AXA, PXA); PYA = fma2(HP2A, AYA, PYA); PZA = fma2(HP2A, AZA, PZA);
    PXB = fma2(HP2B, AXB, PXB); PYB = fma2(HP2B, AYB, PYB); PZB = fma2(HP2B, AZB, PZB);

    // ---- store (rows 2i trail, 2i+1 lead: 48 contiguous 16B-aligned bytes) ----
    {
        float qxl, qxt, qyl, qyt, qzl, qzt, pxl, pxt, pyl, pyt, pzl, pzt;
        upk(XA, qxl, qxt);  upk(YA, qyl, qyt);  upk(ZA, qzl, qzt);
        upk(PXA, pxl, pxt); upk(PYA, pyl, pyt); upk(PZA, pzl, pzt);
        float4* op = reinterpret_cast<float4*>(out + 12 * (size_t)iA);
        op[0] = make_float4(qxt, qyt, qzt, pxt);
        op[1] = make_float4(pyt, pzt, qxl, qyl);
        op[2] = make_float4(qzl, pxl, pyl, pzl);
    }
    if (hasB) {
        float qxl, qxt, qyl, qyt, qzl, qzt, pxl, pxt, pyl, pyt, pzl, pzt;
        upk(XB, qxl, qxt);  upk(YB, qyl, qyt);  upk(ZB, qzl, qzt);
        upk(PXB, pxl, pxt); upk(PYB, pyl, pyt); upk(PZB, pzl, pzt);
        float4* op = reinterpret_cast<float4*>(out + 12 * (size_t)iB);
        op[0] = make_float4(qxt, qyt, qzt, pxt);
        op[1] = make_float4(pyt, pzt, qxl, qyl);
        op[2] = make_float4(qzl, pxl, pyl, pzl);
    }
}

extern "C" void kernel_launch(void* const* d_in, const int* in_sizes, int n_in,
                              void* d_out, int out_size) {
    const float* ts      = (const float*)d_in[0];
    const float* w_lead  = (const float*)d_in[1];
    const float* w_trail = (const float*)d_in[2];
    const int*   n_steps = (const int*)d_in[3];
    float* out = (float*)d_out;

    int n = in_sizes[0];
    int half = (n + 1) / 2;
    int block = 32;
    int grid = (half + block - 1) / block;  // 1024 blocks @ N=65536 -> 6.92/SM
    leapfrog4_kernel<<<grid, block>>>(ts, w_lead, w_trail, n_steps, out, n);
}

// round 8
// speedup vs baseline: 1.0455x; 1.0455x over previous
#include <cuda_runtime.h>

// Leapfrog integrator, softened central potential:
//   accel(q) = -q / (r*(r+1)^2 + 1e-12)
//
// R7: instruction-count attack. Identity r(r+1)^2 = r*(r^2+1) + 2r^2 lets the
// two denominator helpers (S+1, 2S+eps) compute in parallel with the RSQ,
// shortening the serial chain. dt is folded into the rcp result (CD = -dt*c)
// so each kick is a single packed FMA and the 3 accel muls disappear.
// Half-kick fusion as before: pre-kick h*a0, full-dt kicks in the loop,
// post-correction +h*a_last reconstructed from the saved CD.
//
// Layout: 2 particle-pairs per thread; each pair = (lead, trail) of one
// particle packed into f32x2 (they share dt). 32768 threads, block=32 ->
// 1024 uniform blocks = 6.92/SM (balanced waves).
//
// Inputs: d_in[0]=ts f32[N], d_in[1]=w0_lead f32[N,6], d_in[2]=w0_trail f32[N,6],
//         d_in[3]=n_steps i32[1]
// Output: f32[2N,6], row 2i = trail_i, row 2i+1 = lead_i.

typedef unsigned long long u64;

__device__ __forceinline__ u64 pk(float lo, float hi) {
    u64 r; asm("mov.b64 %0, {%1,%2};" : "=l"(r) : "f"(lo), "f"(hi)); return r;
}
__device__ __forceinline__ void upk(u64 v, float& lo, float& hi) {
    asm("mov.b64 {%0,%1}, %2;" : "=f"(lo), "=f"(hi) : "l"(v));
}
__device__ __forceinline__ u64 fma2(u64 a, u64 b, u64 c) {
    u64 d; asm("fma.rn.f32x2 %0, %1, %2, %3;" : "=l"(d) : "l"(a), "l"(b), "l"(c)); return d;
}
__device__ __forceinline__ u64 mul2(u64 a, u64 b) {
    u64 d; asm("mul.rn.f32x2 %0, %1, %2;" : "=l"(d) : "l"(a), "l"(b)); return d;
}
__device__ __forceinline__ u64 add2(u64 a, u64 b) {
    u64 d; asm("add.rn.f32x2 %0, %1, %2;" : "=l"(d) : "l"(a), "l"(b)); return d;
}
__device__ __forceinline__ float frsqrt_fast(float x) {
    float r; asm("rsqrt.approx.f32 %0, %1;" : "=f"(r) : "f"(x)); return r;
}
__device__ __forceinline__ float frcp_fast(float x) {
    float r; asm("rcp.approx.f32 %0, %1;" : "=f"(r) : "f"(x)); return r;
}

// Compute CD = -dt / (r(r+1)^2 + eps), packed, for one pair.
// SP1 = S+1 and W = 2S+eps run in parallel with the RSQ (off critical path).
#define ACCEL_CD(X, Y, Z, CD, DTN2)                        \
    do {                                                   \
        u64 S_ = mul2(X, X);                               \
        S_ = fma2(Y, Y, S_);                               \
        S_ = fma2(Z, Z, S_);                               \
        u64 SP1_ = add2(S_, ONE2);                         \
        u64 W_   = fma2(TWO2, S_, EPS2);                   \
        float s0_, s1_; upk(S_, s0_, s1_);                 \
        u64 RI_ = pk(frsqrt_fast(s0_), frsqrt_fast(s1_));  \
        u64 R_  = mul2(S_, RI_);                           \
        u64 D_  = fma2(R_, SP1_, W_);                      \
        float d0_, d1_; upk(D_, d0_, d1_);                 \
        u64 C_  = pk(frcp_fast(d0_), frcp_fast(d1_));      \
        CD = mul2(C_, DTN2);                               \
    } while (0)

// drift + accel + full kick (fused half-kicks), one pair
#define STEP(X, Y, Z, PX, PY, PZ, CD, DT2, DTN2)           \
    do {                                                   \
        X = fma2(DT2, PX, X);                              \
        Y = fma2(DT2, PY, Y);                              \
        Z = fma2(DT2, PZ, Z);                              \
        ACCEL_CD(X, Y, Z, CD, DTN2);                       \
        PX = fma2(CD, X, PX);                              \
        PY = fma2(CD, Y, PY);                              \
        PZ = fma2(CD, Z, PZ);                              \
    } while (0)

__global__ void __launch_bounds__(32)
leapfrog7_kernel(const float* __restrict__ ts,
                 const float* __restrict__ w_lead,
                 const float* __restrict__ w_trail,
                 const int* __restrict__ n_steps_p,
                 float* __restrict__ out,
                 int n) {
    int idx  = blockIdx.x * 32 + threadIdx.x;
    int half = (n + 1) >> 1;
    if (idx >= half) return;

    const int iA = idx;
    const int iB = idx + half;
    const bool hasB = (iB < n);
    const int iBc = hasB ? iB : iA;

    const int nst = *n_steps_p;
    const float t_f = ts[n - 1] + 0.001f;

    const u64 ONE2 = pk(1.0f, 1.0f);
    const u64 TWO2 = pk(2.0f, 2.0f);
    const u64 EPS2 = pk(1e-12f, 1e-12f);
    const u64 NH2  = pk(-0.5f, -0.5f);

    // ---- load pair A (lead lo, trail hi) ----
    float dtA = (t_f - ts[iA]) / (float)nst;
    const float2* lpA = reinterpret_cast<const float2*>(w_lead  + 6 * (size_t)iA);
    const float2* tpA = reinterpret_cast<const float2*>(w_trail + 6 * (size_t)iA);
    float2 a0 = lpA[0], a1 = lpA[1], a2 = lpA[2];
    float2 b0 = tpA[0], b1 = tpA[1], b2 = tpA[2];
    u64 XA  = pk(a0.x, b0.x), YA  = pk(a0.y, b0.y), ZA  = pk(a1.x, b1.x);
    u64 PXA = pk(a1.y, b1.y), PYA = pk(a2.x, b2.x), PZA = pk(a2.y, b2.y);
    const u64 DT2A  = pk(dtA, dtA);
    const u64 DTN2A = pk(-dtA, -dtA);
    const u64 HN2A  = pk(-0.5f * dtA, -0.5f * dtA);

    // ---- load pair B ----
    float dtB = (t_f - ts[iBc]) / (float)nst;
    const float2* lpB = reinterpret_cast<const float2*>(w_lead  + 6 * (size_t)iBc);
    const float2* tpB = reinterpret_cast<const float2*>(w_trail + 6 * (size_t)iBc);
    float2 c0 = lpB[0], c1 = lpB[1], c2 = lpB[2];
    float2 d0 = tpB[0], d1 = tpB[1], d2 = tpB[2];
    u64 XB  = pk(c0.x, d0.x), YB  = pk(c0.y, d0.y), ZB  = pk(c1.x, d1.x);
    u64 PXB = pk(c1.y, d1.y), PYB = pk(c2.x, d2.x), PZB = pk(c2.y, d2.y);
    const u64 DT2B  = pk(dtB, dtB);
    const u64 DTN2B = pk(-dtB, -dtB);
    const u64 HN2B  = pk(-0.5f * dtB, -0.5f * dtB);

    u64 CDA, CDB;

    // pre-kick: p += h * a(q0)  ->  p = fma(c*(-h), q, p)
    ACCEL_CD(XA, YA, ZA, CDA, HN2A);
    ACCEL_CD(XB, YB, ZB, CDB, HN2B);
    PXA = fma2(CDA, XA, PXA); PYA = fma2(CDA, YA, PYA); PZA = fma2(CDA, ZA, PZA);
    PXB = fma2(CDB, XB, PXB); PYB = fma2(CDB, YB, PYB); PZB = fma2(CDB, ZB, PZB);

    if (nst == 64) {
#pragma unroll 8
        for (int s = 0; s < 64; s++) {
            STEP(XA, YA, ZA, PXA, PYA, PZA, CDA, DT2A, DTN2A);
            STEP(XB, YB, ZB, PXB, PYB, PZB, CDB, DT2B, DTN2B);
        }
    } else {
#pragma unroll 2
        for (int s = 0; s < nst; s++) {
            STEP(XA, YA, ZA, PXA, PYA, PZA, CDA, DT2A, DTN2A);
            STEP(XB, YB, ZB, PXB, PYB, PZB, CDB, DT2B, DTN2B);
        }
    }

    // post-correction: loop kicked full dt at last accel, want half:
    // p += h*a_last = fma(CD * (-0.5), q, p)   (CD = -dt*c -> CD*(-0.5) = h*c... sign:
    // h*a = -h*c*q = (CD*0.5... CD*(-0.5) = 0.5*dt*c; a=-c*q so want p -= h*c*q
    // i.e. p = fma(-h*c, q, p) = fma(CD*0.5, q, p). Loop applied fma(CD, q, p)
    // (full -dt*c); correction removes half: p = fma(CD*(-0.5), q, p).
    {
        u64 KA = mul2(CDA, NH2);
        u64 KB = mul2(CDB, NH2);
        PXA = fma2(KA, XA, PXA); PYA = fma2(KA, YA, PYA); PZA = fma2(KA, ZA, PZA);
        PXB = fma2(KB, XB, PXB); PYB = fma2(KB, YB, PYB); PZB = fma2(KB, ZB, PZB);
    }

    // ---- store: rows 2i (trail) / 2i+1 (lead) = 48 contiguous 16B-aligned bytes
    {
        float qxl, qxt, qyl, qyt, qzl, qzt, pxl, pxt, pyl, pyt, pzl, pzt;
        upk(XA, qxl, qxt);  upk(YA, qyl, qyt);  upk(ZA, qzl, qzt);
        upk(PXA, pxl, pxt); upk(PYA, pyl, pyt); upk(PZA, pzl, pzt);
        float4* op = reinterpret_cast<float4*>(out + 12 * (size_t)iA);
        op[0] = make_float4(qxt, qyt, qzt, pxt);
        op[1] = make_float4(pyt, pzt, qxl, qyl);
        op[2] = make_float4(qzl, pxl, pyl, pzl);
    }
    if (hasB) {
        float qxl, qxt, qyl, qyt, qzl, qzt, pxl, pxt, pyl, pyt, pzl, pzt;
        upk(XB, qxl, qxt);  upk(YB, qyl, qyt);  upk(ZB, qzl, qzt);
        upk(PXB, pxl, pxt); upk(PYB, pyl, pyt); upk(PZB, pzl, pzt);
        float4* op = reinterpret_cast<float4*>(out + 12 * (size_t)iB);
        op[0] = make_float4(qxt, qyt, qzt, pxt);
        op[1] = make_float4(pyt, pzt, qxl, qyl);
        op[2] = make_float4(qzl, pxl, pyl, pzl);
    }
}

extern "C" void kernel_launch(void* const* d_in, const int* in_sizes, int n_in,
                              void* d_out, int out_size) {
    const float* ts      = (const float*)d_in[0];
    const float* w_lead  = (const float*)d_in[1];
    const float* w_trail = (const float*)d_in[2];
    const int*   n_steps = (const int*)d_in[3];
    float* out = (float*)d_out;

    int n = in_sizes[0];
    int half = (n + 1) / 2;
    int block = 32;
    int grid = (half + block - 1) / block;  // 1024 blocks @ N=65536
    leapfrog7_kernel<<<grid, block>>>(ts, w_lead, w_trail, n_steps, out, n);
}

// round 9
// speedup vs baseline: 1.0757x; 1.0290x over previous
#include <cuda_runtime.h>

// Leapfrog integrator, softened central potential:
//   accel(q) = -q / (r*(r+1)^2 + 1e-12)
//
// R8: MUFU + MOV diet.
//  - Batched reciprocal: one RCP serves both lanes of a packed pair
//    (1/d0 = rcp(d0*d1)*d1), MUFU/pair-step 4 -> 3.
//  - Denominator computed scalar after a single unpack of S
//    (r(r+1)^2 + eps = r*(S+1) + 2S + eps), removing packed SP1/W ops
//    and half the pk/upk MOV traffic.
//  - State/drift/kick stay f32x2; 2 independent particle-pairs per thread
//    for ILP; 1024 uniform blocks of 32 (6.92/SM).
//
// Inputs: d_in[0]=ts f32[N], d_in[1]=w0_lead f32[N,6], d_in[2]=w0_trail f32[N,6],
//         d_in[3]=n_steps i32[1]
// Output: f32[2N,6], row 2i = trail_i, row 2i+1 = lead_i.

typedef unsigned long long u64;

__device__ __forceinline__ u64 pk(float lo, float hi) {
    u64 r; asm("mov.b64 %0, {%1,%2};" : "=l"(r) : "f"(lo), "f"(hi)); return r;
}
__device__ __forceinline__ void upk(u64 v, float& lo, float& hi) {
    asm("mov.b64 {%0,%1}, %2;" : "=f"(lo), "=f"(hi) : "l"(v));
}
__device__ __forceinline__ u64 fma2(u64 a, u64 b, u64 c) {
    u64 d; asm("fma.rn.f32x2 %0, %1, %2, %3;" : "=l"(d) : "l"(a), "l"(b), "l"(c)); return d;
}
__device__ __forceinline__ u64 mul2(u64 a, u64 b) {
    u64 d; asm("mul.rn.f32x2 %0, %1, %2;" : "=l"(d) : "l"(a), "l"(b)); return d;
}
__device__ __forceinline__ float frsqrt_fast(float x) {
    float r; asm("rsqrt.approx.f32 %0, %1;" : "=f"(r) : "f"(x)); return r;
}
__device__ __forceinline__ float frcp_fast(float x) {
    float r; asm("rcp.approx.f32 %0, %1;" : "=f"(r) : "f"(x)); return r;
}

// CD = dtn / (r(r+1)^2 + eps) per lane, packed. dtn is a scalar step constant
// (-dt in the loop, -h for the pre-kick). One RCP serves both lanes.
#define ACCEL_CD(X, Y, Z, CD, dtn)                                  \
    do {                                                            \
        u64 S_ = mul2(X, X);                                        \
        S_ = fma2(Y, Y, S_);                                        \
        S_ = fma2(Z, Z, S_);                                        \
        float s0_, s1_; upk(S_, s0_, s1_);                          \
        float ri0_ = frsqrt_fast(s0_);                              \
        float ri1_ = frsqrt_fast(s1_);                              \
        float d0_ = fmaf(s0_ * ri0_, s0_ + 1.0f,                    \
                         fmaf(2.0f, s0_, 1e-12f));                  \
        float d1_ = fmaf(s1_ * ri1_, s1_ + 1.0f,                    \
                         fmaf(2.0f, s1_, 1e-12f));                  \
        float rc_ = frcp_fast(d0_ * d1_);                           \
        float t_  = (dtn) * rc_;                                    \
        CD = pk(t_ * d1_, t_ * d0_);                                \
    } while (0)

// drift + accel + full kick (fused half-kicks), one pair
#define STEP(X, Y, Z, PX, PY, PZ, CD, DT2, dtn)            \
    do {                                                   \
        X = fma2(DT2, PX, X);                              \
        Y = fma2(DT2, PY, Y);                              \
        Z = fma2(DT2, PZ, Z);                              \
        ACCEL_CD(X, Y, Z, CD, dtn);                        \
        PX = fma2(CD, X, PX);                              \
        PY = fma2(CD, Y, PY);                              \
        PZ = fma2(CD, Z, PZ);                              \
    } while (0)

__global__ void __launch_bounds__(32)
leapfrog8_kernel(const float* __restrict__ ts,
                 const float* __restrict__ w_lead,
                 const float* __restrict__ w_trail,
                 const int* __restrict__ n_steps_p,
                 float* __restrict__ out,
                 int n) {
    int idx  = blockIdx.x * 32 + threadIdx.x;
    int half = (n + 1) >> 1;
    if (idx >= half) return;

    const int iA = idx;
    const int iB = idx + half;
    const bool hasB = (iB < n);
    const int iBc = hasB ? iB : iA;

    const int nst = *n_steps_p;
    const float t_f = ts[n - 1] + 0.001f;

    const u64 NH2 = pk(-0.5f, -0.5f);

    // ---- load pair A (lead lo, trail hi) ----
    float dtA  = (t_f - ts[iA]) / (float)nst;
    float dtnA = -dtA;
    float hnA  = -0.5f * dtA;
    const float2* lpA = reinterpret_cast<const float2*>(w_lead  + 6 * (size_t)iA);
    const float2* tpA = reinterpret_cast<const float2*>(w_trail + 6 * (size_t)iA);
    float2 a0 = lpA[0], a1 = lpA[1], a2 = lpA[2];
    float2 b0 = tpA[0], b1 = tpA[1], b2 = tpA[2];
    u64 XA  = pk(a0.x, b0.x), YA  = pk(a0.y, b0.y), ZA  = pk(a1.x, b1.x);
    u64 PXA = pk(a1.y, b1.y), PYA = pk(a2.x, b2.x), PZA = pk(a2.y, b2.y);
    const u64 DT2A = pk(dtA, dtA);

    // ---- load pair B ----
    float dtB  = (t_f - ts[iBc]) / (float)nst;
    float dtnB = -dtB;
    float hnB  = -0.5f * dtB;
    const float2* lpB = reinterpret_cast<const float2*>(w_lead  + 6 * (size_t)iBc);
    const float2* tpB = reinterpret_cast<const float2*>(w_trail + 6 * (size_t)iBc);
    float2 c0 = lpB[0], c1 = lpB[1], c2 = lpB[2];
    float2 d0v = tpB[0], d1v = tpB[1], d2v = tpB[2];
    u64 XB  = pk(c0.x, d0v.x), YB  = pk(c0.y, d0v.y), ZB  = pk(c1.x, d1v.x);
    u64 PXB = pk(c1.y, d1v.y), PYB = pk(c2.x, d2v.x), PZB = pk(c2.y, d2v.y);
    const u64 DT2B = pk(dtB, dtB);

    u64 CDA, CDB;

    // pre-kick: p += h*a(q0)  ->  p = fma(CD, q, p) with CD = -h*c
    ACCEL_CD(XA, YA, ZA, CDA, hnA);
    ACCEL_CD(XB, YB, ZB, CDB, hnB);
    PXA = fma2(CDA, XA, PXA); PYA = fma2(CDA, YA, PYA); PZA = fma2(CDA, ZA, PZA);
    PXB = fma2(CDB, XB, PXB); PYB = fma2(CDB, YB, PYB); PZB = fma2(CDB, ZB, PZB);

    if (nst == 64) {
#pragma unroll 8
        for (int s = 0; s < 64; s++) {
            STEP(XA, YA, ZA, PXA, PYA, PZA, CDA, DT2A, dtnA);
            STEP(XB, YB, ZB, PXB, PYB, PZB, CDB, DT2B, dtnB);
        }
    } else {
#pragma unroll 2
        for (int s = 0; s < nst; s++) {
            STEP(XA, YA, ZA, PXA, PYA, PZA, CDA, DT2A, dtnA);
            STEP(XB, YB, ZB, PXB, PYB, PZB, CDB, DT2B, dtnB);
        }
    }

    // post-correction: loop over-kicked full dt at the last accel; restore to
    // half: p += h*a_last = fma(-0.5*CD, q, p)  (CD = -dt*c)
    {
        u64 KA = mul2(CDA, NH2);
        u64 KB = mul2(CDB, NH2);
        PXA = fma2(KA, XA, PXA); PYA = fma2(KA, YA, PYA); PZA = fma2(KA, ZA, PZA);
        PXB = fma2(KB, XB, PXB); PYB = fma2(KB, YB, PYB); PZB = fma2(KB, ZB, PZB);
    }

    // ---- store: rows 2i (trail) / 2i+1 (lead) = 48 contiguous 16B-aligned bytes
    {
        float qxl, qxt, qyl, qyt, qzl, qzt, pxl, pxt, pyl, pyt, pzl, pzt;
        upk(XA, qxl, qxt);  upk(YA, qyl, qyt);  upk(ZA, qzl, qzt);
        upk(PXA, pxl, pxt); upk(PYA, pyl, pyt); upk(PZA, pzl, pzt);
        float4* op = reinterpret_cast<float4*>(out + 12 * (size_t)iA);
        op[0] = make_float4(qxt, qyt, qzt, pxt);
        op[1] = make_float4(pyt, pzt, qxl, qyl);
        op[2] = make_float4(qzl, pxl, pyl, pzl);
    }
    if (hasB) {
        float qxl, qxt, qyl, qyt, qzl, qzt, pxl, pxt, pyl, pyt, pzl, pzt;
        upk(XB, qxl, qxt);  upk(YB, qyl, qyt);  upk(ZB, qzl, qzt);
        upk(PXB, pxl, pxt); upk(PYB, pyl, pyt); upk(PZB, pzl, pzt);
        float4* op = reinterpret_cast<float4*>(out + 12 * (size_t)iB);
        op[0] = make_float4(qxt, qyt, qzt, pxt);
        op[1] = make_float4(pyt, pzt, qxl, qyl);
        op[2] = make_float4(qzl, pxl, pyl, pzl);
    }
}

extern "C" void kernel_launch(void* const* d_in, const int* in_sizes, int n_in,
                              void* d_out, int out_size) {
    const float* ts      = (const float*)d_in[0];
    const float* w_lead  = (const float*)d_in[1];
    const float* w_trail = (const float*)d_in[2];
    const int*   n_steps = (const int*)d_in[3];
    float* out = (float*)d_out;

    int n = in_sizes[0];
    int half = (n + 1) / 2;
    int block = 32;
    int grid = (half + block - 1) / block;  // 1024 blocks @ N=65536
    leapfrog8_kernel<<<grid, block>>>(ts, w_lead, w_trail, n_steps, out, n);
}